// round 1
// baseline (speedup 1.0000x reference)
#include <cuda_runtime.h>
#include <math.h>

#define Tt 2
#define Nn 10000
#define Ee 30000
#define Dd 64
#define LN_EPS 1e-5f

// ---------------- scratch (no allocations allowed) ----------------
__device__ float g_UT[(size_t)Nn * Dd * Dd];   // UT[n][k][i] = U_n[i][k]  (164 MB)
__device__ float g_hfused[Nn * Dd];
__device__ float g_agg[Nn * Dd];
__device__ int   g_idx[Tt * 2 * Ee];
__device__ int   g_is64;

// ---------------- index dtype detection + conversion ----------------
__global__ void detect_kernel(const int* p) {
    __shared__ int any;
    if (threadIdx.x == 0) any = 0;
    __syncthreads();
    // If data is little-endian int64 with values in [0,10000), every odd
    // 32-bit word is 0. Scan 500 of them (4 KB, safe for either dtype).
    for (int i = threadIdx.x; i < 500; i += blockDim.x)
        if (p[2 * i + 1] != 0) any = 1;
    __syncthreads();
    if (threadIdx.x == 0) g_is64 = (any == 0);
}

__global__ void convert_kernel(const void* src) {
    int i = blockIdx.x * blockDim.x + threadIdx.x;
    if (i >= Tt * 2 * Ee) return;
    if (g_is64) g_idx[i] = (int)((const long long*)src)[i];
    else        g_idx[i] = ((const int*)src)[i];
}

// ---------------- fuse: h_fused = h_prev + h_seq[t]; zero agg ----------------
__global__ void fuse_kernel(const float* __restrict__ hseq_t,
                            const float* __restrict__ hprev) {
    int i = blockIdx.x * blockDim.x + threadIdx.x;
    if (i < Nn * Dd) {
        g_hfused[i] = hprev[i] + hseq_t[i];
        g_agg[i] = 0.f;
    }
}

// ---------------- Householder frames; writes UT (k-major) ----------------
__global__ void __launch_bounds__(64) frames_kernel(const float* __restrict__ fW,
                                                    const float* __restrict__ fb) {
    int n = blockIdx.x, tid = threadIdx.x;
    __shared__ float sh[64];
    __shared__ float sv[4][64];
    __shared__ float snorm[4];
    __shared__ float sT[64 * 65];

    sh[tid] = g_hfused[n * 64 + tid];
    __syncthreads();

    // v[k][tid] = h . fW[:, k*64+tid] + fb
#pragma unroll
    for (int k = 0; k < 4; k++) {
        float acc = fb[k * 64 + tid];
#pragma unroll 8
        for (int d = 0; d < 64; d++) acc += sh[d] * fW[d * 256 + k * 64 + tid];
        sv[k][tid] = acc;
    }
    __syncthreads();
    if (tid < 4) {
        float s = 0.f;
        for (int d = 0; d < 64; d++) s += sv[tid][d] * sv[tid][d];
        snorm[tid] = sqrtf(s) + 1e-8f;
    }
    __syncthreads();
#pragma unroll
    for (int k = 0; k < 4; k++) sv[k][tid] /= snorm[k];
    __syncthreads();

    // thread `tid` owns column e=tid of U: u[d] = U[d][e]
    float u[64];
#pragma unroll
    for (int d = 0; d < 64; d++) u[d] = (d == tid) ? 1.f : 0.f;
#pragma unroll
    for (int k = 0; k < 4; k++) {
        float vU = 0.f;
#pragma unroll
        for (int d = 0; d < 64; d++) vU += sv[k][d] * u[d];
        float c = 2.f * vU;
#pragma unroll
        for (int d = 0; d < 64; d++) u[d] -= c * sv[k][d];
    }
    // UT[n][tid][d] = U[d][tid] = u[d]; transpose via padded smem for coalesced STG
#pragma unroll
    for (int d = 0; d < 64; d++) sT[d * 65 + tid] = u[d];
    __syncthreads();
    float* g = g_UT + (size_t)n * 4096;
#pragma unroll 8
    for (int it = 0; it < 64; it++) g[it * 64 + tid] = sT[tid * 65 + it];
}

// ---------------- per-edge: Q = U_r U_c^T, h_trans, msg MLP, scatter ----------------
__global__ void __launch_bounds__(64) edge_kernel(int t,
                                                  const float* __restrict__ W1,
                                                  const float* __restrict__ b1,
                                                  const float* __restrict__ W2,
                                                  const float* __restrict__ b2,
                                                  float* __restrict__ Qout) {
    int e = blockIdx.x;
    int tid = threadIdx.x;
    __shared__ __align__(16) float sA[64 * 64];  // sA[k*64+i] = UT_row[k][i] = U_r[i][k]
    __shared__ __align__(16) float sB[64 * 64];  // sB[k*64+j] = U_c[j][k]
    __shared__ float sHr[64], sHc[64], sHt[64], sM1[64];

    int row = g_idx[t * 2 * Ee + e];
    int col = g_idx[t * 2 * Ee + Ee + e];

    const float4* gA = (const float4*)(g_UT + (size_t)row * 4096);
    const float4* gB = (const float4*)(g_UT + (size_t)col * 4096);
    float4* s4A = (float4*)sA;
    float4* s4B = (float4*)sB;
#pragma unroll
    for (int i = 0; i < 16; i++) {
        s4A[tid + i * 64] = gA[tid + i * 64];
        s4B[tid + i * 64] = gB[tid + i * 64];
    }
    sHr[tid] = g_hfused[row * 64 + tid];
    sHc[tid] = g_hfused[col * 64 + tid];
    __syncthreads();

    // 8x8 register tile per thread, packed f32x2 FMA
    int ti = tid >> 3, tj = tid & 7;
    int i0 = ti * 8, j0 = tj * 8;
    unsigned long long acc2[8][4];
#pragma unroll
    for (int a = 0; a < 8; a++)
#pragma unroll
        for (int p = 0; p < 4; p++) acc2[a][p] = 0ULL;

#pragma unroll 4
    for (int k = 0; k < 64; k++) {
        float4 af0 = *(const float4*)&sA[k * 64 + i0];
        float4 af1 = *(const float4*)&sA[k * 64 + i0 + 4];
        ulonglong2 bl0 = *(const ulonglong2*)&sB[k * 64 + j0];
        ulonglong2 bl1 = *(const ulonglong2*)&sB[k * 64 + j0 + 4];
        unsigned long long bv0 = bl0.x, bv1 = bl0.y, bv2 = bl1.x, bv3 = bl1.y;
        float av[8] = {af0.x, af0.y, af0.z, af0.w, af1.x, af1.y, af1.z, af1.w};
#pragma unroll
        for (int ii = 0; ii < 8; ii++) {
            unsigned long long a2;
            asm("mov.b64 %0, {%1, %1};" : "=l"(a2) : "f"(av[ii]));
            asm("fma.rn.f32x2 %0, %1, %2, %0;" : "+l"(acc2[ii][0]) : "l"(a2), "l"(bv0));
            asm("fma.rn.f32x2 %0, %1, %2, %0;" : "+l"(acc2[ii][1]) : "l"(a2), "l"(bv1));
            asm("fma.rn.f32x2 %0, %1, %2, %0;" : "+l"(acc2[ii][2]) : "l"(a2), "l"(bv2));
            asm("fma.rn.f32x2 %0, %1, %2, %0;" : "+l"(acc2[ii][3]) : "l"(a2), "l"(bv3));
        }
    }

    // unpack, write Q, accumulate h_trans = Q @ h_col
    float* qbase = Qout + (size_t)e * 4096;
#pragma unroll
    for (int ii = 0; ii < 8; ii++) {
        float q[8];
#pragma unroll
        for (int p = 0; p < 4; p++)
            asm("mov.b64 {%0, %1}, %2;" : "=f"(q[2 * p]), "=f"(q[2 * p + 1]) : "l"(acc2[ii][p]));
        *(float4*)&qbase[(i0 + ii) * 64 + j0]     = make_float4(q[0], q[1], q[2], q[3]);
        *(float4*)&qbase[(i0 + ii) * 64 + j0 + 4] = make_float4(q[4], q[5], q[6], q[7]);
        float p = 0.f;
#pragma unroll
        for (int jj = 0; jj < 8; jj++) p += q[jj] * sHc[j0 + jj];
        p += __shfl_down_sync(0xffffffffu, p, 4, 8);
        p += __shfl_down_sync(0xffffffffu, p, 2, 8);
        p += __shfl_down_sync(0xffffffffu, p, 1, 8);
        if (tj == 0) sHt[i0 + ii] = p;
    }
    __syncthreads();

    // msg = relu([h_row, h_trans] @ W1 + b1) @ W2 + b2
    float m = b1[tid];
#pragma unroll 8
    for (int kk = 0; kk < 64; kk++) m += sHr[kk] * W1[kk * 64 + tid];
#pragma unroll 8
    for (int kk = 0; kk < 64; kk++) m += sHt[kk] * W1[(64 + kk) * 64 + tid];
    m = fmaxf(m, 0.f);
    sM1[tid] = m;
    __syncthreads();
    float m2 = b2[tid];
#pragma unroll 8
    for (int kk = 0; kk < 64; kk++) m2 += sM1[kk] * W2[kk * 64 + tid];
    atomicAdd(&g_agg[(size_t)row * 64 + tid], m2);
}

// ---------------- GRU update + LayerNorm ----------------
__global__ void __launch_bounds__(64) gru_kernel(const float* __restrict__ Wx,
                                                 const float* __restrict__ Wh,
                                                 const float* __restrict__ gb,
                                                 const float* __restrict__ gamma,
                                                 const float* __restrict__ beta,
                                                 float* __restrict__ out_h,
                                                 float* __restrict__ out_last) {
    int n = blockIdx.x, tid = threadIdx.x;
    __shared__ float sa[64], sh[64], rs[64];
    sa[tid] = g_agg[n * 64 + tid];
    sh[tid] = g_hfused[n * 64 + tid];
    __syncthreads();

    float gxz = 0, gxr = 0, gxn = 0, ghz = 0, ghr = 0, ghn = 0;
#pragma unroll 4
    for (int d = 0; d < 64; d++) {
        float a = sa[d], h = sh[d];
        const float* wx = Wx + d * 192;
        const float* wh = Wh + d * 192;
        gxz += a * wx[tid];       ghz += h * wh[tid];
        gxr += a * wx[64 + tid];  ghr += h * wh[64 + tid];
        gxn += a * wx[128 + tid]; ghn += h * wh[128 + tid];
    }
    float z  = 1.f / (1.f + expf(-(gxz + ghz + gb[tid])));
    float r  = 1.f / (1.f + expf(-(gxr + ghr + gb[64 + tid])));
    float nn = tanhf(gxn + r * ghn + gb[128 + tid]);
    float hn = (1.f - z) * nn + z * sh[tid];

    // two-pass LayerNorm
    rs[tid] = hn;
    __syncthreads();
    for (int s = 32; s > 0; s >>= 1) {
        if (tid < s) rs[tid] += rs[tid + s];
        __syncthreads();
    }
    float mu = rs[0] * (1.f / 64.f);
    __syncthreads();
    float dctr = hn - mu;
    rs[tid] = dctr * dctr;
    __syncthreads();
    for (int s = 32; s > 0; s >>= 1) {
        if (tid < s) rs[tid] += rs[tid + s];
        __syncthreads();
    }
    float var = rs[0] * (1.f / 64.f);
    float o = dctr * rsqrtf(var + LN_EPS) * gamma[tid] + beta[tid];
    out_h[n * 64 + tid] = o;
    if (out_last) out_last[n * 64 + tid] = o;
}

// ---------------- dis = ||h_new[row] - Q h_new[col]||^2 ----------------
__global__ void __launch_bounds__(64) dis_kernel(int t,
                                                 const float* __restrict__ Qbase,
                                                 const float* __restrict__ hnew,
                                                 float* __restrict__ dout) {
    int e = blockIdx.x, tid = threadIdx.x;
    __shared__ float sQ[64 * 65];
    __shared__ float shr[64], shc[64], red[64];
    int row = g_idx[t * 2 * Ee + e];
    int col = g_idx[t * 2 * Ee + Ee + e];
    const float* q = Qbase + (size_t)e * 4096;
#pragma unroll 8
    for (int it = 0; it < 64; it++) sQ[it * 65 + tid] = q[it * 64 + tid];
    shr[tid] = hnew[row * 64 + tid];
    shc[tid] = hnew[col * 64 + tid];
    __syncthreads();
    float y = 0.f;
#pragma unroll 8
    for (int j = 0; j < 64; j++) y += sQ[tid * 65 + j] * shc[j];
    float d = shr[tid] - y;
    red[tid] = d * d;
    __syncthreads();
    for (int s = 32; s > 0; s >>= 1) {
        if (tid < s) red[tid] += red[tid + s];
        __syncthreads();
    }
    if (tid == 0) dout[e] = red[0];
}

// ---------------- launch ----------------
extern "C" void kernel_launch(void* const* d_in, const int* in_sizes, int n_in,
                              void* d_out, int out_size) {
    const float* hseq = (const float*)d_in[0];
    const void*  ei   = d_in[1];
    const float* fW   = (const float*)d_in[2];
    const float* fb   = (const float*)d_in[3];
    const float* W1   = (const float*)d_in[4];
    const float* b1   = (const float*)d_in[5];
    const float* W2   = (const float*)d_in[6];
    const float* b2   = (const float*)d_in[7];
    const float* Wx   = (const float*)d_in[8];
    const float* Wh   = (const float*)d_in[9];
    const float* gb   = (const float*)d_in[10];
    const float* gamma = (const float*)d_in[11];
    const float* beta  = (const float*)d_in[12];

    float* out = (float*)d_out;
    float* out_hlast = out;                                    // N*D
    float* out_allh  = out + (size_t)Nn * Dd;                  // T*N*D
    float* out_alld  = out_allh + (size_t)Tt * Nn * Dd;        // T*E
    float* out_allq  = out_alld + (size_t)Tt * Ee;             // T*E*D*D

    detect_kernel<<<1, 256>>>((const int*)ei);
    convert_kernel<<<(Tt * 2 * Ee + 255) / 256, 256>>>(ei);

    for (int t = 0; t < Tt; t++) {
        const float* hprev = (t == 0) ? hseq : (out_allh + (size_t)(t - 1) * Nn * Dd);
        fuse_kernel<<<(Nn * Dd + 255) / 256, 256>>>(hseq + (size_t)t * Nn * Dd, hprev);
        frames_kernel<<<Nn, 64>>>(fW, fb);
        edge_kernel<<<Ee, 64>>>(t, W1, b1, W2, b2, out_allq + (size_t)t * Ee * 4096);
        gru_kernel<<<Nn, 64>>>(Wx, Wh, gb, gamma, beta,
                               out_allh + (size_t)t * Nn * Dd,
                               (t == Tt - 1) ? out_hlast : nullptr);
        dis_kernel<<<Ee, 64>>>(t, out_allq + (size_t)t * Ee * 4096,
                               out_allh + (size_t)t * Nn * Dd,
                               out_alld + (size_t)t * Ee);
    }
}

// round 2
// speedup vs baseline: 2.2072x; 2.2072x over previous
#include <cuda_runtime.h>
#include <math.h>

#define Tt 2
#define Nn 10000
#define Ee 30000
#define LN_EPS 1e-5f

// ---------------- scratch (no allocations allowed) ----------------
__device__ float g_V[(size_t)Nn * 256];   // V[n][a][i], a=reflection, i=dim
__device__ float g_P[(size_t)Nn * 256];   // P = V*T (compact WY):  U = I - P V^T
__device__ float g_hfused[Nn * 64];
__device__ float g_agg[Nn * 64];
__device__ float g_w[Nn * 64];            // w_n = U_n^T h_new[n]
__device__ int   g_idx[Tt * 2 * Ee];
__device__ int   g_is64;

// ---------------- index dtype detection + conversion ----------------
__global__ void detect_kernel(const int* p) {
    __shared__ int any;
    if (threadIdx.x == 0) any = 0;
    __syncthreads();
    for (int i = threadIdx.x; i < 500; i += blockDim.x)
        if (p[2 * i + 1] != 0) any = 1;
    __syncthreads();
    if (threadIdx.x == 0) g_is64 = (any == 0);
}

__global__ void convert_kernel(const void* src) {
    int i = blockIdx.x * blockDim.x + threadIdx.x;
    if (i >= Tt * 2 * Ee) return;
    if (g_is64) g_idx[i] = (int)((const long long*)src)[i];
    else        g_idx[i] = ((const int*)src)[i];
}

// ---------------- fuse: h_fused = h_prev + h_seq[t]; zero agg ----------------
__global__ void fuse_kernel(const float* __restrict__ hseq_t,
                            const float* __restrict__ hprev) {
    int i = blockIdx.x * blockDim.x + threadIdx.x;
    if (i < Nn * 64) {
        g_hfused[i] = hprev[i] + hseq_t[i];
        g_agg[i] = 0.f;
    }
}

// ---------------- frames: compute V, P (compact WY), no dense U ----------------
__global__ void __launch_bounds__(64) frames_kernel(const float* __restrict__ fW,
                                                    const float* __restrict__ fb) {
    int n = blockIdx.x, tid = threadIdx.x;
    __shared__ float sh[64];
    __shared__ float sv[4][64];
    __shared__ float sdot[4][4];
    __shared__ float sT[4][4];
    __shared__ float snorm[4];

    sh[tid] = g_hfused[n * 64 + tid];
    __syncthreads();

    float vloc[4];
#pragma unroll
    for (int a = 0; a < 4; a++) {
        int col = a * 64 + tid;
        float acc = fb[col];
#pragma unroll 8
        for (int d = 0; d < 64; d++) acc += sh[d] * fW[d * 256 + col];
        vloc[a] = acc;
        sv[a][tid] = acc;
    }
    __syncthreads();
    if (tid < 4) {
        float s = 0.f;
        for (int d = 0; d < 64; d++) s += sv[tid][d] * sv[tid][d];
        snorm[tid] = sqrtf(s) + 1e-8f;
    }
    __syncthreads();
#pragma unroll
    for (int a = 0; a < 4; a++) { vloc[a] /= snorm[a]; sv[a][tid] = vloc[a]; }
    __syncthreads();

    // pairwise dots d[j][k] = v_j . v_k (j>k)
    if (tid < 6) {
        const int pj[6] = {1, 2, 2, 3, 3, 3}, pk[6] = {0, 0, 1, 0, 1, 2};
        int j = pj[tid], k = pk[tid];
        float s = 0.f;
        for (int d = 0; d < 64; d++) s += sv[j][d] * sv[k][d];
        sdot[j][k] = s;
    }
    __syncthreads();
    // T: lower-triangular, diag=2, row j: T[j][i] = -2 * sum_{k=i..j-1} d[j][k] T[k][i]
    if (tid == 0) {
        for (int j = 0; j < 4; j++) {
            for (int i = 0; i < j; i++) {
                float z = 0.f;
                for (int k = i; k < j; k++) z += sdot[j][k] * sT[k][i];
                sT[j][i] = -2.f * z;
            }
            sT[j][j] = 2.f;
            for (int i = j + 1; i < 4; i++) sT[j][i] = 0.f;
        }
    }
    __syncthreads();

    float* gV = g_V + (size_t)n * 256;
    float* gP = g_P + (size_t)n * 256;
#pragma unroll
    for (int a = 0; a < 4; a++) {
        float p = 0.f;
#pragma unroll
        for (int k = 0; k < 4; k++) p += vloc[k] * sT[k][a];  // T[k][a]=0 for k<a
        gP[a * 64 + tid] = p;
        gV[a * 64 + tid] = vloc[a];
    }
}

// ---------------- per-edge: Q via rank-4 factors, h_trans, msg MLP, scatter ----------------
__global__ void __launch_bounds__(64) edge_kernel(int t,
                                                  const float* __restrict__ W1,
                                                  const float* __restrict__ b1,
                                                  const float* __restrict__ W2,
                                                  const float* __restrict__ b2,
                                                  float* __restrict__ Qout) {
    int e = blockIdx.x, tid = threadIdx.x;
    __shared__ float4 sPr4[64];              // Pr[i][0..3]
    __shared__ float4 sX4[64];               // X[i][a] = (Pr*G)[i][a] - Vc[i][a]
    __shared__ float sVr[4][64], sPc[4][64], sVc[4][64], sPrRaw[4][64];
    __shared__ float sHr[64], sHc[64], sHt[64], sM1[64], sG[16], sS[8];

    int row = g_idx[t * 2 * Ee + e];
    int col = g_idx[t * 2 * Ee + Ee + e];
    const float* gVr = g_V + (size_t)row * 256;
    const float* gPr = g_P + (size_t)row * 256;
    const float* gVc = g_V + (size_t)col * 256;
    const float* gPc = g_P + (size_t)col * 256;
#pragma unroll
    for (int a = 0; a < 4; a++) {
        sVr[a][tid]    = gVr[a * 64 + tid];
        sPrRaw[a][tid] = gPr[a * 64 + tid];
        sVc[a][tid]    = gVc[a * 64 + tid];
        sPc[a][tid]    = gPc[a * 64 + tid];
    }
    sHr[tid] = g_hfused[row * 64 + tid];
    sHc[tid] = g_hfused[col * 64 + tid];
    __syncthreads();

    // G[a][b] = Vr^T Vc  (16 threads), s1 = Vr^T h_c, s2 = Pc^T h_c (8 threads)
    if (tid < 16) {
        int a = tid >> 2, b = tid & 3;
        float s = 0.f;
        for (int i = 0; i < 64; i++) s += sVr[a][i] * sVc[b][i];
        sG[tid] = s;
    } else if (tid < 24) {
        int a = tid - 16;
        float s = 0.f;
        if (a < 4) { for (int i = 0; i < 64; i++) s += sVr[a][i] * sHc[i]; }
        else       { int b = a - 4; for (int i = 0; i < 64; i++) s += sPc[b][i] * sHc[i]; }
        sS[a] = s;
    }
    __syncthreads();

    // per-row precompute: Pr[i][:], X[i][:] = (Pr G)[i][:] - Vc[i][:], and h_trans[i]
    {
        float pr[4];
#pragma unroll
        for (int a = 0; a < 4; a++) pr[a] = sPrRaw[a][tid];
        float x[4];
#pragma unroll
        for (int b = 0; b < 4; b++) {
            float s = 0.f;
#pragma unroll
            for (int a = 0; a < 4; a++) s += pr[a] * sG[a * 4 + b];
            x[b] = s - sVc[b][tid];
        }
        sPr4[tid] = make_float4(pr[0], pr[1], pr[2], pr[3]);
        sX4[tid]  = make_float4(x[0], x[1], x[2], x[3]);
        float ht = sHc[tid];
#pragma unroll
        for (int a = 0; a < 4; a++) ht += -pr[a] * sS[a] + x[a] * sS[4 + a];
        sHt[tid] = ht;
    }
    __syncthreads();

    // Q[i][j] = delta_ij - sum_a Pr[i][a] Vr[j][a] + sum_a X[i][a] Pc[j][a]
    {
        float vr[4], pc[4];
#pragma unroll
        for (int a = 0; a < 4; a++) { vr[a] = sVr[a][tid]; pc[a] = sPc[a][tid]; }
        float* qcol = Qout + (size_t)e * 4096 + tid;
#pragma unroll 8
        for (int i = 0; i < 64; i++) {
            float4 pr = sPr4[i], x = sX4[i];
            float q = (i == tid) ? 1.f : 0.f;
            q -= pr.x * vr[0] + pr.y * vr[1] + pr.z * vr[2] + pr.w * vr[3];
            q += x.x * pc[0] + x.y * pc[1] + x.z * pc[2] + x.w * pc[3];
            qcol[i * 64] = q;
        }
    }

    // msg = relu([h_row, h_trans] @ W1 + b1) @ W2 + b2
    float m = b1[tid];
#pragma unroll 8
    for (int kk = 0; kk < 64; kk++) m += sHr[kk] * W1[kk * 64 + tid];
#pragma unroll 8
    for (int kk = 0; kk < 64; kk++) m += sHt[kk] * W1[(64 + kk) * 64 + tid];
    m = fmaxf(m, 0.f);
    sM1[tid] = m;
    __syncthreads();
    float m2 = b2[tid];
#pragma unroll 8
    for (int kk = 0; kk < 64; kk++) m2 += sM1[kk] * W2[kk * 64 + tid];
    atomicAdd(&g_agg[(size_t)row * 64 + tid], m2);
}

// ---------------- GRU update + LayerNorm + w = U^T h_new ----------------
__global__ void __launch_bounds__(64) gru_kernel(const float* __restrict__ Wx,
                                                 const float* __restrict__ Wh,
                                                 const float* __restrict__ gb,
                                                 const float* __restrict__ gamma,
                                                 const float* __restrict__ beta,
                                                 float* __restrict__ out_h,
                                                 float* __restrict__ out_last) {
    int n = blockIdx.x, tid = threadIdx.x;
    __shared__ float sa[64], sh[64], rs[64], ss[4];
    sa[tid] = g_agg[n * 64 + tid];
    sh[tid] = g_hfused[n * 64 + tid];
    __syncthreads();

    float gxz = 0, gxr = 0, gxn = 0, ghz = 0, ghr = 0, ghn = 0;
#pragma unroll 4
    for (int d = 0; d < 64; d++) {
        float a = sa[d], h = sh[d];
        const float* wx = Wx + d * 192;
        const float* wh = Wh + d * 192;
        gxz += a * wx[tid];       ghz += h * wh[tid];
        gxr += a * wx[64 + tid];  ghr += h * wh[64 + tid];
        gxn += a * wx[128 + tid]; ghn += h * wh[128 + tid];
    }
    float z  = 1.f / (1.f + expf(-(gxz + ghz + gb[tid])));
    float r  = 1.f / (1.f + expf(-(gxr + ghr + gb[64 + tid])));
    float nn = tanhf(gxn + r * ghn + gb[128 + tid]);
    float hn = (1.f - z) * nn + z * sh[tid];

    // two-pass LayerNorm
    rs[tid] = hn;
    __syncthreads();
    for (int s = 32; s > 0; s >>= 1) {
        if (tid < s) rs[tid] += rs[tid + s];
        __syncthreads();
    }
    float mu = rs[0] * (1.f / 64.f);
    __syncthreads();
    float dctr = hn - mu;
    rs[tid] = dctr * dctr;
    __syncthreads();
    for (int s = 32; s > 0; s >>= 1) {
        if (tid < s) rs[tid] += rs[tid + s];
        __syncthreads();
    }
    float var = rs[0] * (1.f / 64.f);
    float o = dctr * rsqrtf(var + LN_EPS) * gamma[tid] + beta[tid];
    out_h[n * 64 + tid] = o;
    if (out_last) out_last[n * 64 + tid] = o;

    // w = h_new - V (P^T h_new)   (U^T = I - V P^T)
    rs[tid] = o;
    __syncthreads();
    const float* gV = g_V + (size_t)n * 256;
    const float* gP = g_P + (size_t)n * 256;
    if (tid < 4) {
        float s = 0.f;
        for (int i = 0; i < 64; i++) s += gP[tid * 64 + i] * rs[i];
        ss[tid] = s;
    }
    __syncthreads();
    float w = o;
#pragma unroll
    for (int a = 0; a < 4; a++) w -= gV[a * 64 + tid] * ss[a];
    g_w[n * 64 + tid] = w;
}

// ---------------- dis = ||w_row - w_col||^2 ----------------
__global__ void __launch_bounds__(256) dis_kernel(int t, float* __restrict__ dout) {
    int e4 = blockIdx.x;            // 4 edges per block, one warp... use 64-thread groups
    int grp = threadIdx.x >> 6;     // 0..3
    int tid = threadIdx.x & 63;
    int e = e4 * 4 + grp;
    __shared__ float red[256];
    float v = 0.f;
    if (e < Ee) {
        int row = g_idx[t * 2 * Ee + e];
        int col = g_idx[t * 2 * Ee + Ee + e];
        float d = g_w[row * 64 + tid] - g_w[col * 64 + tid];
        v = d * d;
    }
    red[threadIdx.x] = v;
    __syncthreads();
    for (int s = 32; s > 0; s >>= 1) {
        if (tid < s) red[threadIdx.x] += red[threadIdx.x + s];
        __syncthreads();
    }
    if (tid == 0 && e < Ee) dout[e] = red[grp * 64];
}

// ---------------- launch ----------------
extern "C" void kernel_launch(void* const* d_in, const int* in_sizes, int n_in,
                              void* d_out, int out_size) {
    const float* hseq = (const float*)d_in[0];
    const void*  ei   = d_in[1];
    const float* fW   = (const float*)d_in[2];
    const float* fb   = (const float*)d_in[3];
    const float* W1   = (const float*)d_in[4];
    const float* b1   = (const float*)d_in[5];
    const float* W2   = (const float*)d_in[6];
    const float* b2   = (const float*)d_in[7];
    const float* Wx   = (const float*)d_in[8];
    const float* Wh   = (const float*)d_in[9];
    const float* gb   = (const float*)d_in[10];
    const float* gamma = (const float*)d_in[11];
    const float* beta  = (const float*)d_in[12];

    float* out = (float*)d_out;
    float* out_hlast = out;                                    // N*D
    float* out_allh  = out + (size_t)Nn * 64;                  // T*N*D
    float* out_alld  = out_allh + (size_t)Tt * Nn * 64;        // T*E
    float* out_allq  = out_alld + (size_t)Tt * Ee;             // T*E*D*D

    detect_kernel<<<1, 256>>>((const int*)ei);
    convert_kernel<<<(Tt * 2 * Ee + 255) / 256, 256>>>(ei);

    for (int t = 0; t < Tt; t++) {
        const float* hprev = (t == 0) ? hseq : (out_allh + (size_t)(t - 1) * Nn * 64);
        fuse_kernel<<<(Nn * 64 + 255) / 256, 256>>>(hseq + (size_t)t * Nn * 64, hprev);
        frames_kernel<<<Nn, 64>>>(fW, fb);
        edge_kernel<<<Ee, 64>>>(t, W1, b1, W2, b2, out_allq + (size_t)t * Ee * 4096);
        gru_kernel<<<Nn, 64>>>(Wx, Wh, gb, gamma, beta,
                               out_allh + (size_t)t * Nn * 64,
                               (t == Tt - 1) ? out_hlast : nullptr);
        dis_kernel<<<(Ee + 3) / 4, 256>>>(t, out_alld + (size_t)t * Ee);
    }
}

// round 3
// speedup vs baseline: 2.3175x; 1.0500x over previous
#include <cuda_runtime.h>
#include <math.h>

#define Tt 2
#define Nn 10000
#define Ee 30000
#define LN_EPS 1e-5f

typedef unsigned long long ull;

// ---------------- scratch ----------------
__device__ float g_V[(size_t)Nn * 256];   // V[n][a*64+i]
__device__ float g_P[(size_t)Nn * 256];   // P[n][a*64+i]:  U = I - P V^T
__device__ float g_hfused[Nn * 64];
__device__ float g_agg[Nn * 64];
__device__ float g_w[Nn * 64];            // w_n = U_n^T h_new[n]
__device__ float g_W1T[64 * 128];         // W1T[o][k] = W1[k][o]
__device__ float g_W2T[64 * 64];
__device__ int   g_idx[Tt * 2 * Ee];
__device__ int   g_is64;

// ---------------- packed f32x2 helpers ----------------
__device__ __forceinline__ ull dup2(float x) {
    ull r; asm("mov.b64 %0, {%1, %1};" : "=l"(r) : "f"(x)); return r;
}
__device__ __forceinline__ ull pk2(float a, float b) {
    ull r; asm("mov.b64 %0, {%1, %2};" : "=l"(r) : "f"(a), "f"(b)); return r;
}
__device__ __forceinline__ void fma2(ull& acc, ull a, ull b) {
    asm("fma.rn.f32x2 %0, %1, %2, %0;" : "+l"(acc) : "l"(a), "l"(b));
}
__device__ __forceinline__ float2 unpk(ull v) {
    float2 r; asm("mov.b64 {%0, %1}, %2;" : "=f"(r.x), "=f"(r.y) : "l"(v)); return r;
}

// ---------------- index dtype detection + conversion ----------------
__global__ void detect_kernel(const int* p) {
    __shared__ int any;
    if (threadIdx.x == 0) any = 0;
    __syncthreads();
    for (int i = threadIdx.x; i < 500; i += blockDim.x)
        if (p[2 * i + 1] != 0) any = 1;
    __syncthreads();
    if (threadIdx.x == 0) g_is64 = (any == 0);
}

__global__ void convert_kernel(const void* src) {
    int i = blockIdx.x * blockDim.x + threadIdx.x;
    if (i >= Tt * 2 * Ee) return;
    if (g_is64) g_idx[i] = (int)((const long long*)src)[i];
    else        g_idx[i] = ((const int*)src)[i];
}

// ---------------- weight transpose (once) ----------------
__global__ void prep_weights(const float* __restrict__ W1, const float* __restrict__ W2) {
    int i = blockIdx.x * 256 + threadIdx.x;
    if (i < 64 * 128) { int o = i >> 7, k = i & 127; g_W1T[o * 128 + k] = W1[k * 64 + o]; }
    if (i < 64 * 64)  { int o = i >> 6, k = i & 63;  g_W2T[o * 64 + k]  = W2[k * 64 + o]; }
}

// ---------------- fuse ----------------
__global__ void fuse_kernel(const float* __restrict__ hseq_t,
                            const float* __restrict__ hprev) {
    int i = blockIdx.x * blockDim.x + threadIdx.x;
    if (i < Nn * 64) {
        g_hfused[i] = hprev[i] + hseq_t[i];
        g_agg[i] = 0.f;
    }
}

// ---------------- frames: 16 nodes/block, fW staged in smem ----------------
// dyn smem: sfW 16384 | sH 1024 | sV 4096 | sdot 256 | sT 256  = 22016 floats
__global__ void __launch_bounds__(512) frames_kernel(const float* __restrict__ fW,
                                                     const float* __restrict__ fb) {
    extern __shared__ __align__(16) float smem[];
    float* sfW  = smem;                 // [64][256]
    float* sH   = sfW + 16384;          // [16][64]
    float* sV   = sH + 1024;            // [16][256]
    float* sdot = sV + 4096;            // [16][16]
    float* sT   = sdot + 256;           // [16][16]

    int tid = threadIdx.x;
    int nbase = blockIdx.x * 16;

    {   // stage fW (64 KB) + h (4 KB)
        const float4* s4 = (const float4*)fW;
        float4* d4 = (float4*)sfW;
#pragma unroll
        for (int i = 0; i < 8; i++) d4[tid + i * 512] = s4[tid + i * 512];
        sH[tid] = g_hfused[nbase * 64 + tid];
        sH[tid + 512] = g_hfused[nbase * 64 + tid + 512];
    }
    __syncthreads();

    int cg = tid & 63, np = tid >> 6;
    int c0 = cg * 4, n0 = np * 2;
    float acc0[4] = {0, 0, 0, 0}, acc1[4] = {0, 0, 0, 0};
    const float* h0 = &sH[n0 * 64];
    const float* h1 = &sH[(n0 + 1) * 64];
#pragma unroll 4
    for (int k = 0; k < 64; k += 4) {
        float4 ha = *(const float4*)&h0[k];
        float4 hb = *(const float4*)&h1[k];
        float va[4] = {ha.x, ha.y, ha.z, ha.w};
        float vb[4] = {hb.x, hb.y, hb.z, hb.w};
#pragma unroll
        for (int kk = 0; kk < 4; kk++) {
            float4 w = *(const float4*)&sfW[(k + kk) * 256 + c0];
            acc0[0] += va[kk] * w.x; acc0[1] += va[kk] * w.y;
            acc0[2] += va[kk] * w.z; acc0[3] += va[kk] * w.w;
            acc1[0] += vb[kk] * w.x; acc1[1] += vb[kk] * w.y;
            acc1[2] += vb[kk] * w.z; acc1[3] += vb[kk] * w.w;
        }
    }
    {
        float4 fbv = *(const float4*)&fb[c0];
        acc0[0] += fbv.x; acc0[1] += fbv.y; acc0[2] += fbv.z; acc0[3] += fbv.w;
        acc1[0] += fbv.x; acc1[1] += fbv.y; acc1[2] += fbv.z; acc1[3] += fbv.w;
    }
    // per-(node,a) norms: 16-lane groups share (np, a)
    float ss0 = acc0[0]*acc0[0]+acc0[1]*acc0[1]+acc0[2]*acc0[2]+acc0[3]*acc0[3];
    float ss1 = acc1[0]*acc1[0]+acc1[1]*acc1[1]+acc1[2]*acc1[2]+acc1[3]*acc1[3];
#pragma unroll
    for (int m = 1; m < 16; m <<= 1) {
        ss0 += __shfl_xor_sync(0xffffffffu, ss0, m);
        ss1 += __shfl_xor_sync(0xffffffffu, ss1, m);
    }
    float rn0 = 1.f / (sqrtf(ss0) + 1e-8f);
    float rn1 = 1.f / (sqrtf(ss1) + 1e-8f);
#pragma unroll
    for (int cc = 0; cc < 4; cc++) {
        sV[n0 * 256 + c0 + cc] = acc0[cc] * rn0;
        sV[(n0 + 1) * 256 + c0 + cc] = acc1[cc] * rn1;
    }
    __syncthreads();

    // pairwise dots: 96 dots x 4 lanes
    if (tid < 384) {
        int did = tid >> 2, l = tid & 3;
        int n = did / 6, p = did - n * 6;
        const int pj[6] = {1, 2, 2, 3, 3, 3}, pk[6] = {0, 0, 1, 0, 1, 2};
        const float* vj = &sV[n * 256 + pj[p] * 64];
        const float* vk = &sV[n * 256 + pk[p] * 64];
        float s = 0.f;
#pragma unroll 4
        for (int i = l; i < 64; i += 4) s += vj[i] * vk[i];
        s += __shfl_xor_sync(0xffffffffu, s, 1);
        s += __shfl_xor_sync(0xffffffffu, s, 2);
        if (l == 0) sdot[n * 16 + pj[p] * 4 + pk[p]] = s;
    }
    __syncthreads();

    if (tid < 16) {
        int n = tid;
        float Tl[4][4];
        for (int j = 0; j < 4; j++) {
            for (int i = 0; i < j; i++) {
                float z = 0.f;
                for (int k = i; k < j; k++) z += sdot[n * 16 + j * 4 + k] * Tl[k][i];
                Tl[j][i] = -2.f * z;
            }
            Tl[j][j] = 2.f;
            for (int i = j + 1; i < 4; i++) Tl[j][i] = 0.f;
        }
        for (int k = 0; k < 4; k++)
            for (int a = 0; a < 4; a++) sT[n * 16 + k * 4 + a] = Tl[k][a];
    }
    __syncthreads();

    // P = V*T, write V & P (col index c0 == a*64+i0)
    int a = c0 >> 6;
#pragma unroll
    for (int idx = 0; idx < 2; idx++) {
        int nl = n0 + idx;
        int ng = nbase + nl;
        float pv[4];
#pragma unroll
        for (int cc = 0; cc < 4; cc++) {
            int i = (c0 & 63) + cc;
            float s = 0.f;
#pragma unroll
            for (int k = 0; k < 4; k++) s += sV[nl * 256 + k * 64 + i] * sT[nl * 16 + k * 4 + a];
            pv[cc] = s;
        }
        *(float4*)&g_P[(size_t)ng * 256 + c0] = make_float4(pv[0], pv[1], pv[2], pv[3]);
        *(float4*)&g_V[(size_t)ng * 256 + c0] = *(float4*)&sV[nl * 256 + c0];
    }
}

// ---------------- edge: 4 edges/block, weights in smem, packed math ----------------
// dyn smem layout (floats): sW1T 64*130 | sW2T 64*66 | 4 x edge-region(1568)
#define EB 4
#define EDGE_SMEM (64 * 130 + 64 * 66 + EB * 1568)
__global__ void __launch_bounds__(256) edge_kernel(int t,
                                                   const float* __restrict__ b1,
                                                   const float* __restrict__ b2,
                                                   float* __restrict__ Qout) {
    extern __shared__ __align__(16) float smem[];
    float* sW1T = smem;                     // padded stride 130
    float* sW2T = sW1T + 64 * 130;          // padded stride 66
    float* sE   = sW2T + 64 * 66;

    int tid = threadIdx.x;
    for (int i = tid; i < 64 * 128; i += 256) {
        int o = i >> 7, k = i & 127;
        sW1T[o * 130 + k] = g_W1T[i];
    }
    for (int i = tid; i < 64 * 64; i += 256) {
        int o = i >> 6, k = i & 63;
        sW2T[o * 66 + k] = g_W2T[i];
    }

    int g = tid >> 6, et = tid & 63;
    float* eb = sE + g * 1568;
    float4* sPr4 = (float4*)eb;             // 64 float4  (256 f)
    float4* sX4  = (float4*)(eb + 256);     // 64 float4
    float* sVr   = eb + 512;                // [4][64]
    float* sVc   = eb + 768;
    float* sPc   = eb + 1024;
    float* sHcat = eb + 1280;               // [128]: h_row | h_trans
    float* sHc   = eb + 1408;               // [64]
    float* sM1   = eb + 1472;               // [64]
    float* sG    = eb + 1536;               // [16]
    float* sS    = eb + 1552;               // [8]

    int e = blockIdx.x * EB + g;
    int row = g_idx[t * 2 * Ee + e];
    int col = g_idx[t * 2 * Ee + Ee + e];
    const float* gVr = g_V + (size_t)row * 256;
    const float* gPr = g_P + (size_t)row * 256;
    const float* gVc = g_V + (size_t)col * 256;
    const float* gPc = g_P + (size_t)col * 256;
    {
        float pr[4];
#pragma unroll
        for (int a = 0; a < 4; a++) {
            sVr[a * 64 + et] = gVr[a * 64 + et];
            sVc[a * 64 + et] = gVc[a * 64 + et];
            sPc[a * 64 + et] = gPc[a * 64 + et];
            pr[a] = gPr[a * 64 + et];
        }
        sPr4[et] = make_float4(pr[0], pr[1], pr[2], pr[3]);
        sHcat[et] = g_hfused[row * 64 + et];
        sHc[et] = g_hfused[col * 64 + et];
    }
    __syncthreads();

    // small dots: G = Vr^T Vc (16 thr), s1 = Vr^T h_c, s2 = Pc^T h_c (8 thr)
    if (et < 16) {
        int a = et >> 2, b = et & 3;
        const float* va = &sVr[a * 64];
        const float* vb = &sVc[b * 64];
        float s = 0.f;
        for (int i = 0; i < 64; i++) s += va[i] * vb[i];
        sG[et] = s;
    } else if (et < 24) {
        int a = et - 16;
        const float* v = (a < 4) ? &sVr[a * 64] : &sPc[(a - 4) * 64];
        float s = 0.f;
        for (int i = 0; i < 64; i++) s += v[i] * sHc[i];
        sS[a] = s;
    }
    __syncthreads();

    // X[i][b] = (Pr G)[i][b] - Vc[i][b];  h_trans
    {
        float4 prv = sPr4[et];
        float prr[4] = {prv.x, prv.y, prv.z, prv.w};
        float x[4];
#pragma unroll
        for (int b = 0; b < 4; b++) {
            float s = 0.f;
#pragma unroll
            for (int a = 0; a < 4; a++) s += prr[a] * sG[a * 4 + b];
            x[b] = s - sVc[b * 64 + et];
        }
        sX4[et] = make_float4(x[0], x[1], x[2], x[3]);
        float ht = sHc[et];
#pragma unroll
        for (int a = 0; a < 4; a++) ht += -prr[a] * sS[a] + x[a] * sS[4 + a];
        sHcat[64 + et] = ht;
    }
    __syncthreads();

    // Q[i][j] = delta - sum_a Pr[i][a] Vr[j][a] + sum_a X[i][a] Pc[j][a]
    {
        int jq = et & 15, ig = et >> 4;
        int j0 = jq * 4;
        ull vrn[4][2], pcp[4][2];
#pragma unroll
        for (int a = 0; a < 4; a++) {
            vrn[a][0] = pk2(-sVr[a * 64 + j0],     -sVr[a * 64 + j0 + 1]);
            vrn[a][1] = pk2(-sVr[a * 64 + j0 + 2], -sVr[a * 64 + j0 + 3]);
            pcp[a][0] = pk2(sPc[a * 64 + j0],      sPc[a * 64 + j0 + 1]);
            pcp[a][1] = pk2(sPc[a * 64 + j0 + 2],  sPc[a * 64 + j0 + 3]);
        }
        float* qbase = Qout + (size_t)e * 4096;
#pragma unroll 4
        for (int r = 0; r < 16; r++) {
            int i = ig * 16 + r;
            float4 prf = sPr4[i];
            float4 xf = sX4[i];
            ull q0 = 0ULL, q1 = 0ULL, d;
            d = dup2(prf.x); fma2(q0, d, vrn[0][0]); fma2(q1, d, vrn[0][1]);
            d = dup2(prf.y); fma2(q0, d, vrn[1][0]); fma2(q1, d, vrn[1][1]);
            d = dup2(prf.z); fma2(q0, d, vrn[2][0]); fma2(q1, d, vrn[2][1]);
            d = dup2(prf.w); fma2(q0, d, vrn[3][0]); fma2(q1, d, vrn[3][1]);
            d = dup2(xf.x);  fma2(q0, d, pcp[0][0]); fma2(q1, d, pcp[0][1]);
            d = dup2(xf.y);  fma2(q0, d, pcp[1][0]); fma2(q1, d, pcp[1][1]);
            d = dup2(xf.z);  fma2(q0, d, pcp[2][0]); fma2(q1, d, pcp[2][1]);
            d = dup2(xf.w);  fma2(q0, d, pcp[3][0]); fma2(q1, d, pcp[3][1]);
            float2 u0 = unpk(q0), u1 = unpk(q1);
            float q[4] = {u0.x, u0.y, u1.x, u1.y};
            if (i >= j0 && i < j0 + 4) q[i - j0] += 1.f;
            *(float4*)&qbase[i * 64 + j0] = make_float4(q[0], q[1], q[2], q[3]);
        }
    }

    // MLP: relu([h_row,h_trans] @ W1 + b1) @ W2 + b2 (packed over k)
    {
        ull acc = 0ULL;
        const float* w1 = &sW1T[et * 130];
#pragma unroll 16
        for (int k = 0; k < 128; k += 2)
            fma2(acc, *(const ull*)&sHcat[k], *(const ull*)&w1[k]);
        float2 u = unpk(acc);
        float m = fmaxf(u.x + u.y + b1[et], 0.f);
        sM1[et] = m;
    }
    __syncthreads();
    {
        ull acc = 0ULL;
        const float* w2 = &sW2T[et * 66];
#pragma unroll 16
        for (int k = 0; k < 64; k += 2)
            fma2(acc, *(const ull*)&sM1[k], *(const ull*)&w2[k]);
        float2 u = unpk(acc);
        float m2 = u.x + u.y + b2[et];
        atomicAdd(&g_agg[(size_t)row * 64 + et], m2);
    }
}

// ---------------- GRU + LN + w : 8 nodes/block, weights staged ----------------
// dyn smem floats: sWx 12288 | sWh 12288 | sa 512 | sh 512 | rs 512 | ssv 32
#define GRU_SMEM (12288 * 2 + 512 * 3 + 32)
__global__ void __launch_bounds__(512) gru_kernel(const float* __restrict__ Wx,
                                                  const float* __restrict__ Wh,
                                                  const float* __restrict__ gb,
                                                  const float* __restrict__ gamma,
                                                  const float* __restrict__ beta,
                                                  float* __restrict__ out_h,
                                                  float* __restrict__ out_last) {
    extern __shared__ __align__(16) float smem[];
    float* sWx = smem;
    float* sWh = sWx + 12288;
    float* sa  = sWh + 12288;   // [8][64]
    float* shb = sa + 512;      // [8][64]
    float* rs  = shb + 512;     // [8][64]
    float* ssv = rs + 512;      // [8][4]

    int tid = threadIdx.x;
    int nbase = blockIdx.x * 8;
    {
        const float4* wx4 = (const float4*)Wx;
        const float4* wh4 = (const float4*)Wh;
        float4* sx4 = (float4*)sWx;
        float4* sh4 = (float4*)sWh;
#pragma unroll
        for (int i = 0; i < 6; i++) {
            sx4[tid + i * 512] = wx4[tid + i * 512];
            sh4[tid + i * 512] = wh4[tid + i * 512];
        }
        sa[tid] = g_agg[nbase * 64 + tid];
        shb[tid] = g_hfused[nbase * 64 + tid];
    }
    __syncthreads();

    int ln = tid >> 6, tn = tid & 63;
    int n = nbase + ln;
    const float* san = &sa[ln * 64];
    const float* shn = &shb[ln * 64];
    float gxz = 0, gxr = 0, gxn = 0, ghz = 0, ghr = 0, ghn = 0;
#pragma unroll 4
    for (int d = 0; d < 64; d++) {
        float a = san[d], h = shn[d];
        const float* wx = &sWx[d * 192];
        const float* wh = &sWh[d * 192];
        gxz += a * wx[tn];        ghz += h * wh[tn];
        gxr += a * wx[64 + tn];   ghr += h * wh[64 + tn];
        gxn += a * wx[128 + tn];  ghn += h * wh[128 + tn];
    }
    float z  = 1.f / (1.f + expf(-(gxz + ghz + gb[tn])));
    float r  = 1.f / (1.f + expf(-(gxr + ghr + gb[64 + tn])));
    float nn = tanhf(gxn + r * ghn + gb[128 + tn]);
    float hn = (1.f - z) * nn + z * shn[tn];

    float* rsn = &rs[ln * 64];
    rsn[tn] = hn;
    __syncthreads();
    for (int s = 32; s > 0; s >>= 1) {
        if (tn < s) rsn[tn] += rsn[tn + s];
        __syncthreads();
    }
    float mu = rsn[0] * (1.f / 64.f);
    __syncthreads();
    float dctr = hn - mu;
    rsn[tn] = dctr * dctr;
    __syncthreads();
    for (int s = 32; s > 0; s >>= 1) {
        if (tn < s) rsn[tn] += rsn[tn + s];
        __syncthreads();
    }
    float var = rsn[0] * (1.f / 64.f);
    float o = dctr * rsqrtf(var + LN_EPS) * gamma[tn] + beta[tn];
    out_h[(size_t)n * 64 + tn] = o;
    if (out_last) out_last[(size_t)n * 64 + tn] = o;

    __syncthreads();
    rsn[tn] = o;
    __syncthreads();
    const float* gV = g_V + (size_t)n * 256;
    const float* gP = g_P + (size_t)n * 256;
    if (tn < 4) {
        float s = 0.f;
        for (int i = 0; i < 64; i++) s += gP[tn * 64 + i] * rsn[i];
        ssv[ln * 4 + tn] = s;
    }
    __syncthreads();
    float w = o;
#pragma unroll
    for (int a = 0; a < 4; a++) w -= gV[a * 64 + tn] * ssv[ln * 4 + a];
    g_w[(size_t)n * 64 + tn] = w;
}

// ---------------- dis = ||w_row - w_col||^2 ----------------
__global__ void __launch_bounds__(256) dis_kernel(int t, float* __restrict__ dout) {
    int grp = threadIdx.x >> 6;
    int tid = threadIdx.x & 63;
    int e = blockIdx.x * 4 + grp;
    __shared__ float red[256];
    float v = 0.f;
    if (e < Ee) {
        int row = g_idx[t * 2 * Ee + e];
        int col = g_idx[t * 2 * Ee + Ee + e];
        float d = g_w[row * 64 + tid] - g_w[col * 64 + tid];
        v = d * d;
    }
    red[threadIdx.x] = v;
    __syncthreads();
    for (int s = 32; s > 0; s >>= 1) {
        if (tid < s) red[threadIdx.x] += red[threadIdx.x + s];
        __syncthreads();
    }
    if (tid == 0 && e < Ee) dout[e] = red[grp * 64];
}

// ---------------- launch ----------------
extern "C" void kernel_launch(void* const* d_in, const int* in_sizes, int n_in,
                              void* d_out, int out_size) {
    const float* hseq = (const float*)d_in[0];
    const void*  ei   = d_in[1];
    const float* fW   = (const float*)d_in[2];
    const float* fb   = (const float*)d_in[3];
    const float* W1   = (const float*)d_in[4];
    const float* b1   = (const float*)d_in[5];
    const float* W2   = (const float*)d_in[6];
    const float* b2   = (const float*)d_in[7];
    const float* Wx   = (const float*)d_in[8];
    const float* Wh   = (const float*)d_in[9];
    const float* gb   = (const float*)d_in[10];
    const float* gamma = (const float*)d_in[11];
    const float* beta  = (const float*)d_in[12];

    float* out = (float*)d_out;
    float* out_hlast = out;
    float* out_allh  = out + (size_t)Nn * 64;
    float* out_alld  = out_allh + (size_t)Tt * Nn * 64;
    float* out_allq  = out_alld + (size_t)Tt * Ee;

    static int attr_done = 0;
    const int frames_smem = 22016 * 4;
    const int edge_smem = EDGE_SMEM * 4;
    const int gru_smem = GRU_SMEM * 4;
    if (!attr_done) {
        cudaFuncSetAttribute(frames_kernel, cudaFuncAttributeMaxDynamicSharedMemorySize, frames_smem);
        cudaFuncSetAttribute(edge_kernel,   cudaFuncAttributeMaxDynamicSharedMemorySize, edge_smem);
        cudaFuncSetAttribute(gru_kernel,    cudaFuncAttributeMaxDynamicSharedMemorySize, gru_smem);
        attr_done = 1;
    }

    detect_kernel<<<1, 256>>>((const int*)ei);
    convert_kernel<<<(Tt * 2 * Ee + 255) / 256, 256>>>(ei);
    prep_weights<<<32, 256>>>(W1, W2);

    for (int t = 0; t < Tt; t++) {
        const float* hprev = (t == 0) ? hseq : (out_allh + (size_t)(t - 1) * Nn * 64);
        fuse_kernel<<<(Nn * 64 + 255) / 256, 256>>>(hseq + (size_t)t * Nn * 64, hprev);
        frames_kernel<<<Nn / 16, 512, frames_smem>>>(fW, fb);
        edge_kernel<<<Ee / EB, 256, edge_smem>>>(t, b1, b2, out_allq + (size_t)t * Ee * 4096);
        gru_kernel<<<Nn / 8, 512, gru_smem>>>(Wx, Wh, gb, gamma, beta,
                                              out_allh + (size_t)t * Nn * 64,
                                              (t == Tt - 1) ? out_hlast : nullptr);
        dis_kernel<<<(Ee + 3) / 4, 256>>>(t, out_alld + (size_t)t * Ee);
    }
}